// round 15
// baseline (speedup 1.0000x reference)
#include <cuda_runtime.h>
#include <cuda_fp16.h>
#include <math.h>

#define BB 256
#define FF 256
#define DD 512
#define NJ3v 51
#define INDIM 34
#define G4 2048       // 4*D gate rows
#define KTOT 1024     // packed K (512 + 512)
#define MCW 563       // D + NJ3
#define NBLK 128
#define NTHR 256
#define WPADK 1032    // weight SMEM k-stride (halves; conflict-free B-frag loads)

// ---------------- static device scratch (no runtime allocation) ----------------
__device__ float g_Xp[(size_t)BB * FF * G4];     // blocked [t][dg64][b256][32]
__device__ __half g_WA16[(size_t)G4 * KTOT];     // [Whh0 | Wcomb]  fp16
__device__ __half g_WB16[(size_t)G4 * KTOT];     // [Wih1 | Whh1]   fp16
__device__ float g_Wx[INDIM * G4];               // embed_W @ Wih0x^T
__device__ float g_bx[G4];
__device__ float g_cpred[G4];
__device__ float g_bias1[G4];
__device__ float g_p0c[BB * G4];
// h states, fp16, k-PERMUTED within each 16-chunk (fragment-friendly layout):
//   j&15 = j15, pair p=j15>>1, bit=j15&1 -> pos = 4*(p&3) + 2*(p>>2) + bit
__device__ __half g_h0[2][BB * DD];
__device__ __half g_h1[2][BB * DD];
__device__ float g_c0[BB * DD];
__device__ float g_c1[BB * DD];
__device__ float g_z1[BB * DD];
__device__ float g_z2[BB * 1024];
__device__ unsigned g_bar2[64];                  // [0], [32]: per-batch-half counters

// ---------------- helpers ----------------
__device__ __forceinline__ float sigf(float x) { return 1.0f / (1.0f + expf(-x)); }

__device__ __forceinline__ void mma16816(float* d,
    unsigned a0, unsigned a1, unsigned a2, unsigned a3,
    unsigned b0, unsigned b1) {
    asm volatile(
        "mma.sync.aligned.m16n8k16.row.col.f32.f16.f16.f32 "
        "{%0,%1,%2,%3}, {%4,%5,%6,%7}, {%8,%9}, {%0,%1,%2,%3};"
        : "+f"(d[0]), "+f"(d[1]), "+f"(d[2]), "+f"(d[3])
        : "r"(a0), "r"(a1), "r"(a2), "r"(a3), "r"(b0), "r"(b1));
}

// ---------------- one-time precompute kernels (off critical path) ----------------

__global__ void wx_kernel(const float* __restrict__ embed_W, const float* __restrict__ Wih0) {
    int idx = blockIdx.x * 256 + threadIdx.x;
    if (idx >= INDIM * G4) return;
    int i = idx / G4, j = idx % G4;
    float s = 0.f;
    const float* wr = Wih0 + (size_t)j * MCW;
    const float* er = embed_W + (size_t)i * DD;
    for (int k = 0; k < DD; k++) s += er[k] * wr[k];
    g_Wx[idx] = s;
}

__global__ void bias_kernel(const float* __restrict__ embed_b, const float* __restrict__ Wih0,
                            const float* __restrict__ bih0, const float* __restrict__ bhh0,
                            const float* __restrict__ bih1, const float* __restrict__ bhh1,
                            const float* __restrict__ dec_b) {
    int j = blockIdx.x * 256 + threadIdx.x;
    if (j >= G4) return;
    const float* wr = Wih0 + (size_t)j * MCW;
    float s = bih0[j] + bhh0[j];
    for (int k = 0; k < DD; k++) s += embed_b[k] * wr[k];
    g_bx[j] = s;
    float cp = 0.f;
    for (int m = 0; m < NJ3v; m++) cp += dec_b[m] * wr[DD + m];
    g_cpred[j] = cp;
    g_bias1[j] = bih1[j] + bhh1[j];
}

__global__ void p0c_kernel(const float* __restrict__ initp, const float* __restrict__ Wih0) {
    int idx = blockIdx.x * 256 + threadIdx.x;
    int b = idx >> 11, j = idx & (G4 - 1);
    const float* wr = Wih0 + (size_t)j * MCW + DD;
    const float* p0 = initp + (size_t)b * 85;
    float s = 0.f;
    for (int m = 0; m < NJ3v; m++) s += p0[m] * wr[m];
    g_p0c[idx] = s;
}

__global__ void packA_kernel(const float* __restrict__ Whh0, const float* __restrict__ Wih0,
                             const float* __restrict__ dec_W) {
    int idx = blockIdx.x * 256 + threadIdx.x;
    int j = idx >> 10, k = idx & (KTOT - 1);
    float v;
    if (k < DD) {
        v = Whh0[(size_t)j * DD + k];
    } else {
        int kk = k - DD;
        const float* wr = Wih0 + (size_t)j * MCW + DD;
        const float* dr = dec_W + (size_t)kk * NJ3v;
        float s = 0.f;
        for (int m = 0; m < NJ3v; m++) s += wr[m] * dr[m];
        v = s;
    }
    g_WA16[idx] = __float2half(v);
}

__global__ void packB_kernel(const float* __restrict__ Wih1, const float* __restrict__ Whh1) {
    int idx = blockIdx.x * 256 + threadIdx.x;
    int j = idx >> 10, k = idx & (KTOT - 1);
    float v = (k < DD) ? Wih1[(size_t)j * DD + k] : Whh1[(size_t)j * DD + (k - DD)];
    g_WB16[idx] = __float2half(v);
}

__global__ void init1_kernel(const float* __restrict__ initp, const float* __restrict__ W,
                             const float* __restrict__ b) {
    int idx = blockIdx.x * 256 + threadIdx.x;
    int bb = idx >> 9, j = idx & (DD - 1);
    float s = b[j];
    const float* ir = initp + (size_t)bb * 85;
    for (int i = 0; i < 85; i++) s += ir[i] * W[(size_t)i * DD + j];
    g_z1[idx] = fmaxf(s, 0.f);
}
__global__ void init2_kernel(const float* __restrict__ W, const float* __restrict__ b) {
    int idx = blockIdx.x * 256 + threadIdx.x;
    int bb = idx >> 10, j = idx & 1023;
    float s = b[j];
    const float* zr = g_z1 + (size_t)bb * DD;
    for (int k = 0; k < DD; k++) s += zr[k] * W[(size_t)k * 1024 + j];
    g_z2[idx] = fmaxf(s, 0.f);
}
__device__ __forceinline__ int kperm(int d) {
    int blk = d >> 4, j15 = d & 15;
    int p = j15 >> 1, bit = j15 & 1;
    return blk * 16 + 4 * (p & 3) + 2 * (p >> 2) + bit;
}
__global__ void init3_kernel(const float* __restrict__ W, const float* __restrict__ b) {
    int idx = blockIdx.x * 256 + threadIdx.x;
    int bb = idx >> 11, j = idx & (G4 - 1);
    float s = b[j];
    const float* zr = g_z2 + (size_t)bb * 1024;
    for (int k = 0; k < 1024; k++) s += zr[k] * W[(size_t)k * G4 + j];
    if (j < DD)            g_h0[0][(size_t)bb * DD + kperm(j)] = __float2half(s);
    else if (j < 2 * DD)   g_h1[0][(size_t)bb * DD + kperm(j - DD)] = __float2half(s);
    else if (j < 3 * DD)   g_c0[(size_t)bb * DD + (j - 2 * DD)] = s;
    else                   g_c1[(size_t)bb * DD + (j - 3 * DD)] = s;
}

// Xp blocked layout: addr = ((t*64 + dg)*256 + b)*32 + g*8 + dl
__global__ void xp_kernel(const float* __restrict__ x) {
    __shared__ float sX[32][INDIM];
    int j = blockIdx.x * 256 + threadIdx.x;  // grid.x = 8
    int r0 = blockIdx.y * 32;
    for (int idx = threadIdx.x; idx < 32 * INDIM; idx += 256) {
        int r = idx / INDIM, i = idx % INDIM;
        int row = r0 + r;
        int tt = row >> 8, b = row & 255;
        sX[r][i] = x[((size_t)b * FF + tt) * INDIM + i];
    }
    __syncthreads();
    float wcol[INDIM];
#pragma unroll
    for (int i = 0; i < INDIM; i++) wcol[i] = g_Wx[i * G4 + j];
    float bxj = g_bx[j], cpj = g_cpred[j];
    int dg = (j & 511) >> 3, dl = j & 7, g = j >> 9;
    int colidx = g * 8 + dl;
    for (int r = 0; r < 32; r++) {
        int row = r0 + r;
        int tt = row >> 8, b = row & 255;
        float acc = bxj + ((tt == 0) ? g_p0c[(size_t)b * G4 + j] : cpj);
#pragma unroll
        for (int i = 0; i < INDIM; i++) acc += sX[r][i] * wcol[i];
        g_Xp[(((size_t)tt * 64 + dg) * 256 + b) * 32 + colidx] = acc;
    }
}

// ---------------- persistent tensor-core recurrent kernel ----------------
// 128 blocks = 64 d-groups x 2 batch halves; weights fp16 SMEM-resident;
// A-fragments via direct LDG.64 from L2 (permuted h layout); 8-deep register
// prefetch ring; zero syncthreads in the k-loop; warp-local barrier wait.

__device__ __forceinline__ void bar_arrive(int bh) {
    __threadfence();   // gpu-scope: publish ALL threads' h writes before release
    if (threadIdx.x == 0) {
        unsigned* bp = &g_bar2[bh * 32];
        asm volatile("red.release.gpu.add.u32 [%0], 1;" :: "l"(bp) : "memory");
    }
}
__device__ __forceinline__ void warp_wait(int bh, unsigned target) {
    if ((threadIdx.x & 31) == 0) {
        unsigned* bp = &g_bar2[bh * 32];
        unsigned v;
        asm volatile("ld.acquire.gpu.u32 %0, [%1];" : "=r"(v) : "l"(bp) : "memory");
        while (v < target) {
            asm volatile("nanosleep.u32 64;");
            asm volatile("ld.acquire.gpu.u32 %0, [%1];" : "=r"(v) : "l"(bp) : "memory");
        }
    }
    __syncwarp();
}

// s0: k-step rotation (0 phase A, 32 phase B) so barrier-safe inputs come first.
// Dependency boundary at local step 32; wait placed at step 24 (ring depth 8).
template<bool ISA>
__device__ __forceinline__ void do_phase(
    int t, int s0, const __half* __restrict__ in0, const __half* __restrict__ in1,
    __half* __restrict__ hout, float* cr, float* __restrict__ mc,
    const __half* sWm, const float* sBias,
    int wm, int g, int tg, int B0, int d0, int dgrp, int hoff,
    int bh, unsigned target)
{
    const int row0 = B0 + wm * 16 + g;
    const int coloff = 4 * tg;

    // gate bases (phase A: Xp from DRAM — issued early; phase B: bias from SMEM)
    float2 xb[4][2];
    if (ISA) {
        const float* xp = g_Xp + ((size_t)t * 64 + dgrp) * (256 * 32);
#pragma unroll
        for (int nt = 0; nt < 4; nt++)
#pragma unroll
            for (int p = 0; p < 2; p++) {
                int bl = wm * 16 + g + p * 8;
                xb[nt][p] = __ldcg((const float2*)&xp[(size_t)(B0 + bl) * 32 + nt * 8 + 2 * tg]);
            }
    } else {
#pragma unroll
        for (int nt = 0; nt < 4; nt++) {
            float2 bv;
            bv.x = sBias[nt * 8 + 2 * tg];
            bv.y = sBias[nt * 8 + 2 * tg + 1];
            xb[nt][0] = bv; xb[nt][1] = bv;
        }
    }

    float acc[4][4];
#pragma unroll
    for (int nt = 0; nt < 4; nt++)
#pragma unroll
        for (int r = 0; r < 4; r++) acc[nt][r] = 0.f;

    uint2 ra[8], rb[8];
    // prologue: prefetch steps 0..7 (all safe: boundary at 32)
#pragma unroll
    for (int sp = 0; sp < 8; sp++) {
        int kk = (sp + s0) & 63;
        const __half* src = (kk < 32) ? in0 : in1;
        size_t off = (size_t)row0 * DD + (kk & 31) * 16 + coloff;
        ra[sp] = __ldcg((const uint2*)(src + off));
        rb[sp] = __ldcg((const uint2*)(src + off + 8 * DD));
    }

    const __half* wbase = sWm + g * WPADK + 2 * tg;
    for (int so = 0; so < 8; so++) {
        if (so == 3 && target) warp_wait(bh, target);  // before first dependent prefetch
        const bool pf = (so < 7);
#pragma unroll
        for (int si = 0; si < 8; si++) {
            int s = so * 8 + si;
            uint2 ua = ra[si], ub = rb[si];
            if (pf) {
                int kkp = (s + 8 + s0) & 63;
                const __half* src = (kkp < 32) ? in0 : in1;
                size_t off = (size_t)row0 * DD + (kkp & 31) * 16 + coloff;
                ra[si] = __ldcg((const uint2*)(src + off));
                rb[si] = __ldcg((const uint2*)(src + off + 8 * DD));
            }
            int kk = (s + s0) & 63;
            const __half* w = wbase + kk * 16;
#pragma unroll
            for (int nt = 0; nt < 4; nt++) {
                const __half* bp = w + nt * (8 * WPADK);
                unsigned b0 = *(const unsigned*)bp;
                unsigned b1 = *(const unsigned*)(bp + 8);
                mma16816(acc[nt], ua.x, ub.x, ua.y, ub.y, b0, b1);
            }
        }
    }

    // register epilogue: thread owns (batch g, g+8) x (d 2tg, 2tg+1), all 4 gates;
    // c-state lives in registers (cr[4]).
#pragma unroll
    for (int p = 0; p < 2; p++) {
        int bl = wm * 16 + g + p * 8;
        float hv[2];
#pragma unroll
        for (int v = 0; v < 2; v++) {
            float gi = acc[0][p * 2 + v] + (v ? xb[0][p].y : xb[0][p].x);
            float gf = acc[1][p * 2 + v] + (v ? xb[1][p].y : xb[1][p].x);
            float gg = acc[2][p * 2 + v] + (v ? xb[2][p].y : xb[2][p].x);
            float go = acc[3][p * 2 + v] + (v ? xb[3][p].y : xb[3][p].x);
            float c = cr[p * 2 + v];
            float cn = sigf(gf) * c + sigf(gi) * tanhf(gg);
            cr[p * 2 + v] = cn;
            hv[v] = sigf(go) * tanhf(cn);
        }
        __half2 hh = __floats2half2_rn(hv[0], hv[1]);
        *(__half2*)&hout[(size_t)(B0 + bl) * DD + hoff] = hh;  // permuted k layout
        if (!ISA) {
            float* mr = mc + ((size_t)(B0 + bl) * FF + t) * MCW + d0 + 2 * tg;
            mr[0] = hv[0]; mr[1] = hv[1];
        }
    }
}

__global__ __launch_bounds__(NTHR, 1) void lstm_persist(float* __restrict__ mc) {
    extern __shared__ __align__(16) unsigned char smraw[];
    __half* sW    = (__half*)smraw;                  // [2][32][WPADK]
    float*  sBias = (float*)(sW + 2 * 32 * WPADK);   // [32]

    const int tid  = threadIdx.x;
    const int lane = tid & 31;
    const int wm   = tid >> 5;          // warp = m-tile of 16 batches
    const int g    = lane >> 2;
    const int tg   = lane & 3;
    const int dgrp = blockIdx.x >> 1;   // 0..63
    const int bh   = blockIdx.x & 1;    // batch half
    const int B0   = bh * 128;
    const int d0   = dgrp * 8;
    const int hoff = (dgrp >> 1) * 16 + 4 * tg + 2 * (dgrp & 1);  // permuted h store

    // one-time: resident fp16 weights (row r = gate*8 + dl), uint4 copies
    for (int i = tid; i < 32 * 128; i += NTHR) {
        int r = i >> 7, c = (i & 127) * 8;
        int grow = (r >> 3) * DD + d0 + (r & 7);
        *(uint4*)&sW[r * WPADK + c] =
            __ldcg((const uint4*)&g_WA16[(size_t)grow * KTOT + c]);
        *(uint4*)&sW[32 * WPADK + r * WPADK + c] =
            __ldcg((const uint4*)&g_WB16[(size_t)grow * KTOT + c]);
    }
    if (tid < 32) sBias[tid] = __ldcg(&g_bias1[(tid >> 3) * DD + d0 + (tid & 7)]);

    // c-state in registers
    float c0r[4], c1r[4];
#pragma unroll
    for (int p = 0; p < 2; p++)
#pragma unroll
        for (int v = 0; v < 2; v++) {
            int bl = wm * 16 + g + p * 8;
            int d = d0 + 2 * tg + v;
            c0r[p * 2 + v] = __ldcg(&g_c0[(size_t)(B0 + bl) * DD + d]);
            c1r[p * 2 + v] = __ldcg(&g_c1[(size_t)(B0 + bl) * DD + d]);
        }
    __syncthreads();

    unsigned ep = 0;
    for (int t = 0; t < FF; t++) {
        int p = t & 1;
        // phase A: layer-0; in = [h0_prev | h1_prev]; safe half = h0 (steps 0-31)
        do_phase<true>(t, 0, g_h0[p], g_h1[p], g_h0[1 - p], c0r, nullptr,
                       sW, sBias, wm, g, tg, B0, d0, dgrp, hoff,
                       bh, ep ? ep * 64u : 0u);
        __syncthreads();
        bar_arrive(bh); ep++;
        // phase B: layer-1; in = [h0_new | h1_prev]; safe half = h1 (rotated first)
        do_phase<false>(t, 32, g_h0[1 - p], g_h1[p], g_h1[1 - p], c1r, mc,
                        sW + 32 * WPADK, sBias, wm, g, tg, B0, d0, dgrp, hoff,
                        bh, ep * 64u);
        __syncthreads();
        bar_arrive(bh); ep++;
    }
}

// ---------------- final decode: preds from stored h1 context ----------------
__global__ __launch_bounds__(256) void dec_kernel(const float* __restrict__ dec_W,
                                                  const float* __restrict__ dec_b,
                                                  float* __restrict__ out_kp, float* __restrict__ mc) {
    __shared__ float sh[4][DD];
    size_t row0 = (size_t)blockIdx.x * 4;
    for (int idx = threadIdx.x; idx < 4 * DD; idx += 256)
        sh[idx >> 9][idx & (DD - 1)] = mc[(row0 + (idx >> 9)) * MCW + (idx & (DD - 1))];
    __syncthreads();
    int r = threadIdx.x >> 6, c = threadIdx.x & 63;
    if (c < NJ3v) {
        float s = dec_b[c];
        for (int k = 0; k < DD; k++) s += sh[r][k] * dec_W[(size_t)k * NJ3v + c];
        size_t row = row0 + r;
        out_kp[row * NJ3v + c] = s;
        mc[row * MCW + DD + c] = s;
    }
}

// ---------------- launch ----------------
extern "C" void kernel_launch(void* const* d_in, const int* in_sizes, int n_in,
                              void* d_out, int out_size) {
    const float* x       = (const float*)d_in[0];
    const float* initp   = (const float*)d_in[1];
    const float* embed_W = (const float*)d_in[2];
    const float* embed_b = (const float*)d_in[3];
    const float* ni_W1   = (const float*)d_in[4];
    const float* ni_b1   = (const float*)d_in[5];
    const float* ni_W2   = (const float*)d_in[6];
    const float* ni_b2   = (const float*)d_in[7];
    const float* ni_W3   = (const float*)d_in[8];
    const float* ni_b3   = (const float*)d_in[9];
    const float* Wih0    = (const float*)d_in[10];
    const float* Whh0    = (const float*)d_in[11];
    const float* bih0    = (const float*)d_in[12];
    const float* bhh0    = (const float*)d_in[13];
    const float* Wih1    = (const float*)d_in[14];
    const float* Whh1    = (const float*)d_in[15];
    const float* bih1    = (const float*)d_in[16];
    const float* bhh1    = (const float*)d_in[17];
    const float* dec_W   = (const float*)d_in[18];
    const float* dec_b   = (const float*)d_in[19];

    float* out = (float*)d_out;
    float* kp = out;                                  // (B,F,17,3)
    float* mc = out + (size_t)BB * FF * NJ3v;         // (B,F,563)

    // one-time precompute (parallel)
    wx_kernel<<<272, 256>>>(embed_W, Wih0);
    bias_kernel<<<8, 256>>>(embed_b, Wih0, bih0, bhh0, bih1, bhh1, dec_b);
    p0c_kernel<<<2048, 256>>>(initp, Wih0);
    packA_kernel<<<8192, 256>>>(Whh0, Wih0, dec_W);
    packB_kernel<<<8192, 256>>>(Wih1, Whh1);
    init1_kernel<<<512, 256>>>(initp, ni_W1, ni_b1);
    init2_kernel<<<1024, 256>>>(ni_W2, ni_b2);
    init3_kernel<<<2048, 256>>>(ni_W3, ni_b3);
    xp_kernel<<<dim3(8, 2048), 256>>>(x);

    // reset split barrier counters (graph-replay deterministic)
    void* barp = nullptr;
    cudaGetSymbolAddress(&barp, g_bar2);
    cudaMemsetAsync(barp, 0, 64 * sizeof(unsigned));

    // persistent tensor-core recurrence
    const int SMEM_TOT = 2 * 32 * WPADK * 2 + 32 * 4;
    static int attr_set = 0;
    if (!attr_set) {
        cudaFuncSetAttribute(lstm_persist, cudaFuncAttributeMaxDynamicSharedMemorySize, SMEM_TOT);
        attr_set = 1;
    }
    lstm_persist<<<NBLK, NTHR, SMEM_TOT>>>(mc);

    // final decode of preds for all (b,t)
    dec_kernel<<<16384, 256>>>(dec_W, dec_b, kp, mc);
}

// round 16
// speedup vs baseline: 1.1322x; 1.1322x over previous
#include <cuda_runtime.h>
#include <cuda_fp16.h>
#include <math.h>

#define BB 256
#define FF 256
#define DD 512
#define NJ3v 51
#define INDIM 34
#define G4 2048       // 4*D gate rows
#define KTOT 1024     // packed K (512 + 512)
#define MCW 563       // D + NJ3
#define NBLK 128
#define NTHR 256
#define WPADK 1032    // weight SMEM k-stride (halves; odd 16B units -> LDSM conflict-free)
#define APAD 72       // input SMEM k-stride (halves; 9x16B units -> LDSM conflict-free)
#define TILEH (128 * APAD)   // halves per input stage buffer

// ---------------- static device scratch (no runtime allocation) ----------------
__device__ float g_Xp[(size_t)BB * FF * G4];     // blocked [t][dg64][b256][32]
__device__ __half g_WA16[(size_t)G4 * KTOT];     // [Whh0 | Wcomb]  fp16
__device__ __half g_WB16[(size_t)G4 * KTOT];     // [Wih1 | Whh1]   fp16
__device__ float g_Wx[INDIM * G4];               // embed_W @ Wih0x^T
__device__ float g_bx[G4];
__device__ float g_cpred[G4];
__device__ float g_bias1[G4];
__device__ float g_p0c[BB * G4];
__device__ __half g_h0[2][BB * DD];              // h states, fp16, plain [b][k]
__device__ __half g_h1[2][BB * DD];
__device__ float g_c0[BB * DD];
__device__ float g_c1[BB * DD];
__device__ float g_z1[BB * DD];
__device__ float g_z2[BB * 1024];
__device__ unsigned g_bar2[64];                  // [0], [32]: per-batch-half counters

// ---------------- helpers ----------------
__device__ __forceinline__ float sigf(float x) { return 1.0f / (1.0f + expf(-x)); }

__device__ __forceinline__ void mma16816(float* d,
    unsigned a0, unsigned a1, unsigned a2, unsigned a3,
    unsigned b0, unsigned b1) {
    asm volatile(
        "mma.sync.aligned.m16n8k16.row.col.f32.f16.f16.f32 "
        "{%0,%1,%2,%3}, {%4,%5,%6,%7}, {%8,%9}, {%0,%1,%2,%3};"
        : "+f"(d[0]), "+f"(d[1]), "+f"(d[2]), "+f"(d[3])
        : "r"(a0), "r"(a1), "r"(a2), "r"(a3), "r"(b0), "r"(b1));
}

__device__ __forceinline__ void ldsm4(unsigned& r0, unsigned& r1, unsigned& r2, unsigned& r3,
                                      unsigned addr) {
    asm volatile("ldmatrix.sync.aligned.m8n8.x4.shared.b16 {%0,%1,%2,%3}, [%4];"
        : "=r"(r0), "=r"(r1), "=r"(r2), "=r"(r3) : "r"(addr));
}

// ---------------- one-time precompute kernels (off critical path) ----------------

__global__ void wx_kernel(const float* __restrict__ embed_W, const float* __restrict__ Wih0) {
    int idx = blockIdx.x * 256 + threadIdx.x;
    if (idx >= INDIM * G4) return;
    int i = idx / G4, j = idx % G4;
    float s = 0.f;
    const float* wr = Wih0 + (size_t)j * MCW;
    const float* er = embed_W + (size_t)i * DD;
    for (int k = 0; k < DD; k++) s += er[k] * wr[k];
    g_Wx[idx] = s;
}

__global__ void bias_kernel(const float* __restrict__ embed_b, const float* __restrict__ Wih0,
                            const float* __restrict__ bih0, const float* __restrict__ bhh0,
                            const float* __restrict__ bih1, const float* __restrict__ bhh1,
                            const float* __restrict__ dec_b) {
    int j = blockIdx.x * 256 + threadIdx.x;
    if (j >= G4) return;
    const float* wr = Wih0 + (size_t)j * MCW;
    float s = bih0[j] + bhh0[j];
    for (int k = 0; k < DD; k++) s += embed_b[k] * wr[k];
    g_bx[j] = s;
    float cp = 0.f;
    for (int m = 0; m < NJ3v; m++) cp += dec_b[m] * wr[DD + m];
    g_cpred[j] = cp;
    g_bias1[j] = bih1[j] + bhh1[j];
}

__global__ void p0c_kernel(const float* __restrict__ initp, const float* __restrict__ Wih0) {
    int idx = blockIdx.x * 256 + threadIdx.x;
    int b = idx >> 11, j = idx & (G4 - 1);
    const float* wr = Wih0 + (size_t)j * MCW + DD;
    const float* p0 = initp + (size_t)b * 85;
    float s = 0.f;
    for (int m = 0; m < NJ3v; m++) s += p0[m] * wr[m];
    g_p0c[idx] = s;
}

__global__ void packA_kernel(const float* __restrict__ Whh0, const float* __restrict__ Wih0,
                             const float* __restrict__ dec_W) {
    int idx = blockIdx.x * 256 + threadIdx.x;
    int j = idx >> 10, k = idx & (KTOT - 1);
    float v;
    if (k < DD) {
        v = Whh0[(size_t)j * DD + k];
    } else {
        int kk = k - DD;
        const float* wr = Wih0 + (size_t)j * MCW + DD;
        const float* dr = dec_W + (size_t)kk * NJ3v;
        float s = 0.f;
        for (int m = 0; m < NJ3v; m++) s += wr[m] * dr[m];
        v = s;
    }
    g_WA16[idx] = __float2half(v);
}

__global__ void packB_kernel(const float* __restrict__ Wih1, const float* __restrict__ Whh1) {
    int idx = blockIdx.x * 256 + threadIdx.x;
    int j = idx >> 10, k = idx & (KTOT - 1);
    float v = (k < DD) ? Wih1[(size_t)j * DD + k] : Whh1[(size_t)j * DD + (k - DD)];
    g_WB16[idx] = __float2half(v);
}

__global__ void init1_kernel(const float* __restrict__ initp, const float* __restrict__ W,
                             const float* __restrict__ b) {
    int idx = blockIdx.x * 256 + threadIdx.x;
    int bb = idx >> 9, j = idx & (DD - 1);
    float s = b[j];
    const float* ir = initp + (size_t)bb * 85;
    for (int i = 0; i < 85; i++) s += ir[i] * W[(size_t)i * DD + j];
    g_z1[idx] = fmaxf(s, 0.f);
}
__global__ void init2_kernel(const float* __restrict__ W, const float* __restrict__ b) {
    int idx = blockIdx.x * 256 + threadIdx.x;
    int bb = idx >> 10, j = idx & 1023;
    float s = b[j];
    const float* zr = g_z1 + (size_t)bb * DD;
    for (int k = 0; k < DD; k++) s += zr[k] * W[(size_t)k * 1024 + j];
    g_z2[idx] = fmaxf(s, 0.f);
}
__global__ void init3_kernel(const float* __restrict__ W, const float* __restrict__ b) {
    int idx = blockIdx.x * 256 + threadIdx.x;
    int bb = idx >> 11, j = idx & (G4 - 1);
    float s = b[j];
    const float* zr = g_z2 + (size_t)bb * 1024;
    for (int k = 0; k < 1024; k++) s += zr[k] * W[(size_t)k * G4 + j];
    if (j < DD)            g_h0[0][(size_t)bb * DD + j] = __float2half(s);
    else if (j < 2 * DD)   g_h1[0][(size_t)bb * DD + (j - DD)] = __float2half(s);
    else if (j < 3 * DD)   g_c0[(size_t)bb * DD + (j - 2 * DD)] = s;
    else                   g_c1[(size_t)bb * DD + (j - 3 * DD)] = s;
}

// Xp blocked layout: addr = ((t*64 + dg)*256 + b)*32 + g*8 + dl
__global__ void xp_kernel(const float* __restrict__ x) {
    __shared__ float sX[32][INDIM];
    int j = blockIdx.x * 256 + threadIdx.x;  // grid.x = 8
    int r0 = blockIdx.y * 32;
    for (int idx = threadIdx.x; idx < 32 * INDIM; idx += 256) {
        int r = idx / INDIM, i = idx % INDIM;
        int row = r0 + r;
        int tt = row >> 8, b = row & 255;
        sX[r][i] = x[((size_t)b * FF + tt) * INDIM + i];
    }
    __syncthreads();
    float wcol[INDIM];
#pragma unroll
    for (int i = 0; i < INDIM; i++) wcol[i] = g_Wx[i * G4 + j];
    float bxj = g_bx[j], cpj = g_cpred[j];
    int dg = (j & 511) >> 3, dl = j & 7, g = j >> 9;
    int colidx = g * 8 + dl;
    for (int r = 0; r < 32; r++) {
        int row = r0 + r;
        int tt = row >> 8, b = row & 255;
        float acc = bxj + ((tt == 0) ? g_p0c[(size_t)b * G4 + j] : cpj);
#pragma unroll
        for (int i = 0; i < INDIM; i++) acc += sX[r][i] * wcol[i];
        g_Xp[(((size_t)tt * 64 + dg) * 256 + b) * 32 + colidx] = acc;
    }
}

// ---------------- persistent tensor-core recurrent kernel ----------------
// 128 blocks = 64 d-groups x 2 batch halves. R13 pipeline (4-stage cp.async,
// one sync/tile, safe-half barrier overlap) + ldmatrix.x4 fragment loads
// (7 instr per k16-chunk instead of 16). c-state in registers.

__device__ __forceinline__ void bar_arrive(int bh) {
    __threadfence();   // publish ALL threads' h writes before the release-arrive
    if (threadIdx.x == 0) {
        unsigned* bp = &g_bar2[bh * 32];
        asm volatile("red.release.gpu.add.u32 [%0], 1;" :: "l"(bp) : "memory");
    }
}
__device__ __forceinline__ void bar_wait(int bh, unsigned target) {
    if (threadIdx.x == 0) {
        unsigned* bp = &g_bar2[bh * 32];
        unsigned v;
        asm volatile("ld.acquire.gpu.u32 %0, [%1];" : "=r"(v) : "l"(bp) : "memory");
        while (v < target) {
            asm volatile("nanosleep.u32 64;");
            asm volatile("ld.acquire.gpu.u32 %0, [%1];" : "=r"(v) : "l"(bp) : "memory");
        }
    }
    __syncthreads();
}

__device__ __forceinline__ void stage_tile(const __half* in0, const __half* in1,
                                           int ktile, __half* dst, int tid, int B0) {
    const __half* src = ((ktile < 8) ? in0 : in1) + (size_t)B0 * DD + (ktile & 7) * 64;
#pragma unroll
    for (int i = 0; i < 4; i++) {
        int id = tid + i * 256;
        int br = id >> 3, ch = id & 7;
        unsigned sa = (unsigned)__cvta_generic_to_shared(dst + br * APAD + ch * 8);
        const void* gp = src + (size_t)br * DD + ch * 8;
        asm volatile("cp.async.cg.shared.global [%0], [%1], 16;" :: "r"(sa), "l"(gp));
    }
    asm volatile("cp.async.commit_group;" ::: "memory");
}

// ldmatrix-based consume of one staged k64 tile.
// abase: u32 smem addr of this warp's A rows in the stage buffer (+lane offset)
// bbase: u32 smem addr of weight rows (+lane offset); kbyte = ktile*128
__device__ __forceinline__ void consume_tile(float acc[4][4],
                                             unsigned abase, unsigned bbase) {
#pragma unroll
    for (int ks = 0; ks < 4; ks++) {
        unsigned a0, a1, a2, a3;
        ldsm4(a0, a1, a2, a3, abase + ks * 32);
        unsigned b0, b1, b2, b3, b4, b5, b6, b7;
        unsigned baddr = bbase + ks * 32;
        ldsm4(b0, b1, b2, b3, baddr);
        ldsm4(b4, b5, b6, b7, baddr + 16 * WPADK * 2);
        mma16816(acc[0], a0, a1, a2, a3, b0, b1);
        mma16816(acc[1], a0, a1, a2, a3, b2, b3);
        mma16816(acc[2], a0, a1, a2, a3, b4, b5);
        mma16816(acc[3], a0, a1, a2, a3, b6, b7);
    }
}

// koff: k-tile rotation (0 phase A, 8 phase B) so the barrier-safe input half
// is staged/consumed first. target==0 -> no barrier wait.
template<bool ISA>
__device__ __forceinline__ void do_phase(
    int t, int koff, const __half* __restrict__ in0, const __half* __restrict__ in1,
    __half* __restrict__ hout, float* cr, float* __restrict__ mc,
    unsigned sWu, unsigned sInu, __half* sIn, const float* sBias,
    int tid, int wm, int g, int tg, int B0, int d0, int dgrp,
    unsigned aoff, unsigned boff,
    int bh, unsigned target)
{
    // gate bases (phase A: Xp from DRAM — issued early; phase B: bias from SMEM)
    float2 xb[4][2];
    if (ISA) {
        const float* xp = g_Xp + ((size_t)t * 64 + dgrp) * (256 * 32);
#pragma unroll
        for (int nt = 0; nt < 4; nt++)
#pragma unroll
            for (int p = 0; p < 2; p++) {
                int bl = wm * 16 + g + p * 8;
                xb[nt][p] = __ldcg((const float2*)&xp[(size_t)(B0 + bl) * 32 + nt * 8 + 2 * tg]);
            }
    } else {
#pragma unroll
        for (int nt = 0; nt < 4; nt++) {
            float2 bv;
            bv.x = sBias[nt * 8 + 2 * tg];
            bv.y = sBias[nt * 8 + 2 * tg + 1];
            xb[nt][0] = bv; xb[nt][1] = bv;
        }
    }

    float acc[4][4];
#pragma unroll
    for (int nt = 0; nt < 4; nt++)
#pragma unroll
        for (int r = 0; r < 4; r++) acc[nt][r] = 0.f;

    // prologue: stage 3 safe tiles
    stage_tile(in0, in1, (0 + koff) & 15, sIn + 0 * TILEH, tid, B0);
    stage_tile(in0, in1, (1 + koff) & 15, sIn + 1 * TILEH, tid, B0);
    stage_tile(in0, in1, (2 + koff) & 15, sIn + 2 * TILEH, tid, B0);

    for (int i = 0; i < 14; i++) {
        if (i == 5 && target) bar_wait(bh, target);   // before first dependent stage
        asm volatile("cp.async.wait_group 2;" ::: "memory");
        __syncthreads();
        stage_tile(in0, in1, (i + 3 + koff) & 15, sIn + ((i + 3) & 3) * TILEH, tid, B0);
        consume_tile(acc, sInu + (unsigned)((i & 3) * TILEH * 2) + aoff,
                     sWu + boff + (unsigned)(((i + koff) & 15) * 128));
    }
    asm volatile("cp.async.wait_group 1;" ::: "memory");
    __syncthreads();
    consume_tile(acc, sInu + (unsigned)((14 & 3) * TILEH * 2) + aoff,
                 sWu + boff + (unsigned)(((14 + koff) & 15) * 128));
    asm volatile("cp.async.wait_group 0;" ::: "memory");
    __syncthreads();
    consume_tile(acc, sInu + (unsigned)((15 & 3) * TILEH * 2) + aoff,
                 sWu + boff + (unsigned)(((15 + koff) & 15) * 128));

    // register epilogue: thread owns (batch g, g+8) x (d 2tg, 2tg+1), all 4 gates;
    // c-state lives in registers (cr[4]).
#pragma unroll
    for (int p = 0; p < 2; p++) {
        int bl = wm * 16 + g + p * 8;
        float hv[2];
#pragma unroll
        for (int v = 0; v < 2; v++) {
            float gi = acc[0][p * 2 + v] + (v ? xb[0][p].y : xb[0][p].x);
            float gf = acc[1][p * 2 + v] + (v ? xb[1][p].y : xb[1][p].x);
            float gg = acc[2][p * 2 + v] + (v ? xb[2][p].y : xb[2][p].x);
            float go = acc[3][p * 2 + v] + (v ? xb[3][p].y : xb[3][p].x);
            float c = cr[p * 2 + v];
            float cn = sigf(gf) * c + sigf(gi) * tanhf(gg);
            cr[p * 2 + v] = cn;
            hv[v] = sigf(go) * tanhf(cn);
        }
        __half2 hh = __floats2half2_rn(hv[0], hv[1]);
        *(__half2*)&hout[(size_t)(B0 + bl) * DD + d0 + 2 * tg] = hh;
        if (!ISA) {
            float* mr = mc + ((size_t)(B0 + bl) * FF + t) * MCW + d0 + 2 * tg;
            mr[0] = hv[0]; mr[1] = hv[1];
        }
    }
}

__global__ __launch_bounds__(NTHR, 1) void lstm_persist(float* __restrict__ mc) {
    extern __shared__ __align__(16) unsigned char smraw[];
    __half* sW    = (__half*)smraw;                  // [2][32][WPADK]
    __half* sIn   = sW + 2 * 32 * WPADK;             // [4][128][APAD]
    float*  sBias = (float*)(sIn + 4 * TILEH);       // [32]

    const int tid  = threadIdx.x;
    const int lane = tid & 31;
    const int wm   = tid >> 5;          // warp = m-tile of 16 batches
    const int g    = lane >> 2;
    const int tg   = lane & 3;
    const int dgrp = blockIdx.x >> 1;   // 0..63
    const int bh   = blockIdx.x & 1;    // batch half
    const int B0   = bh * 128;
    const int d0   = dgrp * 8;

    const unsigned sWu  = (unsigned)__cvta_generic_to_shared(sW);
    const unsigned sInu = (unsigned)__cvta_generic_to_shared(sIn);
    // ldmatrix lane offsets (bytes)
    const unsigned aoff = (unsigned)(((wm * 16 + (lane & 15)) * APAD + ((lane >> 4) << 3)) * 2);
    const unsigned boff = (unsigned)(((((lane >> 1) & 8) | (lane & 7)) * WPADK + (lane & 8)) * 2);

    // one-time: resident fp16 weights (row r = gate*8 + dl), uint4 copies
    for (int i = tid; i < 32 * 128; i += NTHR) {
        int r = i >> 7, c = (i & 127) * 8;
        int grow = (r >> 3) * DD + d0 + (r & 7);
        *(uint4*)&sW[r * WPADK + c] =
            __ldcg((const uint4*)&g_WA16[(size_t)grow * KTOT + c]);
        *(uint4*)&sW[32 * WPADK + r * WPADK + c] =
            __ldcg((const uint4*)&g_WB16[(size_t)grow * KTOT + c]);
    }
    if (tid < 32) sBias[tid] = __ldcg(&g_bias1[(tid >> 3) * DD + d0 + (tid & 7)]);

    // c-state in registers
    float c0r[4], c1r[4];
#pragma unroll
    for (int p = 0; p < 2; p++)
#pragma unroll
        for (int v = 0; v < 2; v++) {
            int bl = wm * 16 + g + p * 8;
            int d = d0 + 2 * tg + v;
            c0r[p * 2 + v] = __ldcg(&g_c0[(size_t)(B0 + bl) * DD + d]);
            c1r[p * 2 + v] = __ldcg(&g_c1[(size_t)(B0 + bl) * DD + d]);
        }
    __syncthreads();

    unsigned ep = 0;
    for (int t = 0; t < FF; t++) {
        int p = t & 1;
        // phase A: layer-0; in = [h0_prev | h1_prev]; safe half = h0 (tiles 0-7)
        do_phase<true>(t, 0, g_h0[p], g_h1[p], g_h0[1 - p], c0r, nullptr,
                       sWu, sInu, sIn, sBias, tid, wm, g, tg, B0, d0, dgrp,
                       aoff, boff, bh, ep ? ep * 64u : 0u);
        __syncthreads();
        bar_arrive(bh); ep++;
        // phase B: layer-1; in = [h0_new | h1_prev]; safe half = h1 (rotated first)
        do_phase<false>(t, 8, g_h0[1 - p], g_h1[p], g_h1[1 - p], c1r, mc,
                        sWu + 32 * WPADK * 2, sInu, sIn, sBias, tid, wm, g, tg, B0, d0, dgrp,
                        aoff, boff, bh, ep * 64u);
        __syncthreads();
        bar_arrive(bh); ep++;
    }
}

// ---------------- final decode: preds from stored h1 context ----------------
__global__ __launch_bounds__(256) void dec_kernel(const float* __restrict__ dec_W,
                                                  const float* __restrict__ dec_b,
                                                  float* __restrict__ out_kp, float* __restrict__ mc) {
    __shared__ float sh[4][DD];
    size_t row0 = (size_t)blockIdx.x * 4;
    for (int idx = threadIdx.x; idx < 4 * DD; idx += 256)
        sh[idx >> 9][idx & (DD - 1)] = mc[(row0 + (idx >> 9)) * MCW + (idx & (DD - 1))];
    __syncthreads();
    int r = threadIdx.x >> 6, c = threadIdx.x & 63;
    if (c < NJ3v) {
        float s = dec_b[c];
        for (int k = 0; k < DD; k++) s += sh[r][k] * dec_W[(size_t)k * NJ3v + c];
        size_t row = row0 + r;
        out_kp[row * NJ3v + c] = s;
        mc[row * MCW + DD + c] = s;
    }
}

// ---------------- launch ----------------
extern "C" void kernel_launch(void* const* d_in, const int* in_sizes, int n_in,
                              void* d_out, int out_size) {
    const float* x       = (const float*)d_in[0];
    const float* initp   = (const float*)d_in[1];
    const float* embed_W = (const float*)d_in[2];
    const float* embed_b = (const float*)d_in[3];
    const float* ni_W1   = (const float*)d_in[4];
    const float* ni_b1   = (const float*)d_in[5];
    const float* ni_W2   = (const float*)d_in[6];
    const float* ni_b2   = (const float*)d_in[7];
    const float* ni_W3   = (const float*)d_in[8];
    const float* ni_b3   = (const float*)d_in[9];
    const float* Wih0    = (const float*)d_in[10];
    const float* Whh0    = (const float*)d_in[11];
    const float* bih0    = (const float*)d_in[12];
    const float* bhh0    = (const float*)d_in[13];
    const float* Wih1    = (const float*)d_in[14];
    const float* Whh1    = (const float*)d_in[15];
    const float* bih1    = (const float*)d_in[16];
    const float* bhh1    = (const float*)d_in[17];
    const float* dec_W   = (const float*)d_in[18];
    const float* dec_b   = (const float*)d_in[19];

    float* out = (float*)d_out;
    float* kp = out;                                  // (B,F,17,3)
    float* mc = out + (size_t)BB * FF * NJ3v;         // (B,F,563)

    // one-time precompute (parallel)
    wx_kernel<<<272, 256>>>(embed_W, Wih0);
    bias_kernel<<<8, 256>>>(embed_b, Wih0, bih0, bhh0, bih1, bhh1, dec_b);
    p0c_kernel<<<2048, 256>>>(initp, Wih0);
    packA_kernel<<<8192, 256>>>(Whh0, Wih0, dec_W);
    packB_kernel<<<8192, 256>>>(Wih1, Whh1);
    init1_kernel<<<512, 256>>>(initp, ni_W1, ni_b1);
    init2_kernel<<<1024, 256>>>(ni_W2, ni_b2);
    init3_kernel<<<2048, 256>>>(ni_W3, ni_b3);
    xp_kernel<<<dim3(8, 2048), 256>>>(x);

    // reset split barrier counters (graph-replay deterministic)
    void* barp = nullptr;
    cudaGetSymbolAddress(&barp, g_bar2);
    cudaMemsetAsync(barp, 0, 64 * sizeof(unsigned));

    // persistent tensor-core recurrence
    const int SMEM_TOT = (2 * 32 * WPADK + 4 * TILEH) * 2 + 32 * 4;
    static int attr_set = 0;
    if (!attr_set) {
        cudaFuncSetAttribute(lstm_persist, cudaFuncAttributeMaxDynamicSharedMemorySize, SMEM_TOT);
        attr_set = 1;
    }
    lstm_persist<<<NBLK, NTHR, SMEM_TOT>>>(mc);

    // final decode of preds for all (b,t)
    dec_kernel<<<16384, 256>>>(dec_W, dec_b, kp, mc);
}

// round 17
// speedup vs baseline: 1.5101x; 1.3338x over previous
#include <cuda_runtime.h>
#include <cuda_fp16.h>
#include <math.h>

#define BB 256
#define FF 256
#define DD 512
#define NJ3v 51
#define INDIM 34
#define G4 2048       // 4*D gate rows
#define KTOT 1024     // packed K (512 + 512)
#define MCW 563       // D + NJ3
#define NBLK 128
#define NTHR 256
#define WPADK 1032    // weight SMEM k-stride (halves; odd 16B units -> LDSM conflict-free)
#define APAD 72       // input SMEM k-stride (halves; 9x16B units -> LDSM conflict-free)
#define WBUFH (16 * APAD)        // halves per warp stage buffer (16 rows)
#define WRING (4 * WBUFH)        // 4-buffer ring per warp

// ---------------- static device scratch (no runtime allocation) ----------------
__device__ float g_Xp[(size_t)BB * FF * G4];     // blocked [t][dg64][b256][32]
__device__ __half g_WA16[(size_t)G4 * KTOT];     // [Whh0 | Wcomb]  fp16
__device__ __half g_WB16[(size_t)G4 * KTOT];     // [Wih1 | Whh1]   fp16
__device__ float g_Wx[INDIM * G4];               // embed_W @ Wih0x^T
__device__ float g_bx[G4];
__device__ float g_cpred[G4];
__device__ float g_bias1[G4];
__device__ float g_p0c[BB * G4];
__device__ __half g_h0[2][BB * DD];              // h states, fp16, plain [b][k]
__device__ __half g_h1[2][BB * DD];
__device__ float g_c0[BB * DD];
__device__ float g_c1[BB * DD];
__device__ float g_z1[BB * DD];
__device__ float g_z2[BB * 1024];
__device__ unsigned g_bar2[64];                  // [0], [32]: per-batch-half counters

// ---------------- helpers ----------------
// fast activations via MUFU (rel err ~1e-7, negligible vs fp16 path)
__device__ __forceinline__ float sigf(float x) {
    return __fdividef(1.0f, 1.0f + __expf(-x));
}
__device__ __forceinline__ float tanhf_f(float x) {
    return __fdividef(2.0f, 1.0f + __expf(-2.0f * x)) - 1.0f;
}

__device__ __forceinline__ void mma16816(float* d,
    unsigned a0, unsigned a1, unsigned a2, unsigned a3,
    unsigned b0, unsigned b1) {
    asm volatile(
        "mma.sync.aligned.m16n8k16.row.col.f32.f16.f16.f32 "
        "{%0,%1,%2,%3}, {%4,%5,%6,%7}, {%8,%9}, {%0,%1,%2,%3};"
        : "+f"(d[0]), "+f"(d[1]), "+f"(d[2]), "+f"(d[3])
        : "r"(a0), "r"(a1), "r"(a2), "r"(a3), "r"(b0), "r"(b1));
}

__device__ __forceinline__ void ldsm4(unsigned& r0, unsigned& r1, unsigned& r2, unsigned& r3,
                                      unsigned addr) {
    asm volatile("ldmatrix.sync.aligned.m8n8.x4.shared.b16 {%0,%1,%2,%3}, [%4];"
        : "=r"(r0), "=r"(r1), "=r"(r2), "=r"(r3) : "r"(addr));
}

// ---------------- one-time precompute kernels (off critical path) ----------------

__global__ void wx_kernel(const float* __restrict__ embed_W, const float* __restrict__ Wih0) {
    int idx = blockIdx.x * 256 + threadIdx.x;
    if (idx >= INDIM * G4) return;
    int i = idx / G4, j = idx % G4;
    float s = 0.f;
    const float* wr = Wih0 + (size_t)j * MCW;
    const float* er = embed_W + (size_t)i * DD;
    for (int k = 0; k < DD; k++) s += er[k] * wr[k];
    g_Wx[idx] = s;
}

__global__ void bias_kernel(const float* __restrict__ embed_b, const float* __restrict__ Wih0,
                            const float* __restrict__ bih0, const float* __restrict__ bhh0,
                            const float* __restrict__ bih1, const float* __restrict__ bhh1,
                            const float* __restrict__ dec_b) {
    int j = blockIdx.x * 256 + threadIdx.x;
    if (j >= G4) return;
    const float* wr = Wih0 + (size_t)j * MCW;
    float s = bih0[j] + bhh0[j];
    for (int k = 0; k < DD; k++) s += embed_b[k] * wr[k];
    g_bx[j] = s;
    float cp = 0.f;
    for (int m = 0; m < NJ3v; m++) cp += dec_b[m] * wr[DD + m];
    g_cpred[j] = cp;
    g_bias1[j] = bih1[j] + bhh1[j];
}

__global__ void p0c_kernel(const float* __restrict__ initp, const float* __restrict__ Wih0) {
    int idx = blockIdx.x * 256 + threadIdx.x;
    int b = idx >> 11, j = idx & (G4 - 1);
    const float* wr = Wih0 + (size_t)j * MCW + DD;
    const float* p0 = initp + (size_t)b * 85;
    float s = 0.f;
    for (int m = 0; m < NJ3v; m++) s += p0[m] * wr[m];
    g_p0c[idx] = s;
}

__global__ void packA_kernel(const float* __restrict__ Whh0, const float* __restrict__ Wih0,
                             const float* __restrict__ dec_W) {
    int idx = blockIdx.x * 256 + threadIdx.x;
    int j = idx >> 10, k = idx & (KTOT - 1);
    float v;
    if (k < DD) {
        v = Whh0[(size_t)j * DD + k];
    } else {
        int kk = k - DD;
        const float* wr = Wih0 + (size_t)j * MCW + DD;
        const float* dr = dec_W + (size_t)kk * NJ3v;
        float s = 0.f;
        for (int m = 0; m < NJ3v; m++) s += wr[m] * dr[m];
        v = s;
    }
    g_WA16[idx] = __float2half(v);
}

__global__ void packB_kernel(const float* __restrict__ Wih1, const float* __restrict__ Whh1) {
    int idx = blockIdx.x * 256 + threadIdx.x;
    int j = idx >> 10, k = idx & (KTOT - 1);
    float v = (k < DD) ? Wih1[(size_t)j * DD + k] : Whh1[(size_t)j * DD + (k - DD)];
    g_WB16[idx] = __float2half(v);
}

__global__ void init1_kernel(const float* __restrict__ initp, const float* __restrict__ W,
                             const float* __restrict__ b) {
    int idx = blockIdx.x * 256 + threadIdx.x;
    int bb = idx >> 9, j = idx & (DD - 1);
    float s = b[j];
    const float* ir = initp + (size_t)bb * 85;
    for (int i = 0; i < 85; i++) s += ir[i] * W[(size_t)i * DD + j];
    g_z1[idx] = fmaxf(s, 0.f);
}
__global__ void init2_kernel(const float* __restrict__ W, const float* __restrict__ b) {
    int idx = blockIdx.x * 256 + threadIdx.x;
    int bb = idx >> 10, j = idx & 1023;
    float s = b[j];
    const float* zr = g_z1 + (size_t)bb * DD;
    for (int k = 0; k < DD; k++) s += zr[k] * W[(size_t)k * 1024 + j];
    g_z2[idx] = fmaxf(s, 0.f);
}
__global__ void init3_kernel(const float* __restrict__ W, const float* __restrict__ b) {
    int idx = blockIdx.x * 256 + threadIdx.x;
    int bb = idx >> 11, j = idx & (G4 - 1);
    float s = b[j];
    const float* zr = g_z2 + (size_t)bb * 1024;
    for (int k = 0; k < 1024; k++) s += zr[k] * W[(size_t)k * G4 + j];
    if (j < DD)            g_h0[0][(size_t)bb * DD + j] = __float2half(s);
    else if (j < 2 * DD)   g_h1[0][(size_t)bb * DD + (j - DD)] = __float2half(s);
    else if (j < 3 * DD)   g_c0[(size_t)bb * DD + (j - 2 * DD)] = s;
    else                   g_c1[(size_t)bb * DD + (j - 3 * DD)] = s;
}

// Xp blocked layout: addr = ((t*64 + dg)*256 + b)*32 + g*8 + dl
__global__ void xp_kernel(const float* __restrict__ x) {
    __shared__ float sX[32][INDIM];
    int j = blockIdx.x * 256 + threadIdx.x;  // grid.x = 8
    int r0 = blockIdx.y * 32;
    for (int idx = threadIdx.x; idx < 32 * INDIM; idx += 256) {
        int r = idx / INDIM, i = idx % INDIM;
        int row = r0 + r;
        int tt = row >> 8, b = row & 255;
        sX[r][i] = x[((size_t)b * FF + tt) * INDIM + i];
    }
    __syncthreads();
    float wcol[INDIM];
#pragma unroll
    for (int i = 0; i < INDIM; i++) wcol[i] = g_Wx[i * G4 + j];
    float bxj = g_bx[j], cpj = g_cpred[j];
    int dg = (j & 511) >> 3, dl = j & 7, g = j >> 9;
    int colidx = g * 8 + dl;
    for (int r = 0; r < 32; r++) {
        int row = r0 + r;
        int tt = row >> 8, b = row & 255;
        float acc = bxj + ((tt == 0) ? g_p0c[(size_t)b * G4 + j] : cpj);
#pragma unroll
        for (int i = 0; i < INDIM; i++) acc += sX[r][i] * wcol[i];
        g_Xp[(((size_t)tt * 64 + dg) * 256 + b) * 32 + colidx] = acc;
    }
}

// ---------------- persistent tensor-core recurrent kernel ----------------
// 128 blocks = 64 d-groups x 2 batch halves. Warp-autonomous k-loop:
// per-warp private A stage ring (cp.async groups), ldmatrix.x4 fragments,
// ZERO block syncs inside the loop; warp-local barrier waits.

__device__ __forceinline__ void bar_arrive(int bh) {
    __threadfence();   // publish ALL threads' h writes before the release-arrive
    if (threadIdx.x == 0) {
        unsigned* bp = &g_bar2[bh * 32];
        asm volatile("red.release.gpu.add.u32 [%0], 1;" :: "l"(bp) : "memory");
    }
}
__device__ __forceinline__ void warp_wait(int bh, unsigned target) {
    if ((threadIdx.x & 31) == 0) {
        unsigned* bp = &g_bar2[bh * 32];
        unsigned v;
        asm volatile("ld.acquire.gpu.u32 %0, [%1];" : "=r"(v) : "l"(bp) : "memory");
        while (v < target) {
            asm volatile("nanosleep.u32 64;");
            asm volatile("ld.acquire.gpu.u32 %0, [%1];" : "=r"(v) : "l"(bp) : "memory");
        }
    }
    __syncwarp();
}

// warp-private stage: this warp's 16 batch rows x 64 k halves into its ring buffer
__device__ __forceinline__ void stage_tile_w(const __half* in0, const __half* in1,
                                             int ktile, unsigned dstu, int lane, int rowbase) {
    const __half* src = ((ktile < 8) ? in0 : in1) + (size_t)rowbase * DD + (ktile & 7) * 64;
#pragma unroll
    for (int i = 0; i < 4; i++) {
        int id = lane + i * 32;
        int row = id >> 3, ch = id & 7;
        unsigned sa = dstu + (unsigned)((row * APAD + ch * 8) * 2);
        const void* gp = src + row * DD + ch * 8;
        asm volatile("cp.async.cg.shared.global [%0], [%1], 16;" :: "r"(sa), "l"(gp));
    }
    asm volatile("cp.async.commit_group;" ::: "memory");
}

__device__ __forceinline__ void consume_tile(float acc[4][4],
                                             unsigned abase, unsigned bbase) {
#pragma unroll
    for (int ks = 0; ks < 4; ks++) {
        unsigned a0, a1, a2, a3;
        ldsm4(a0, a1, a2, a3, abase + ks * 32);
        unsigned b0, b1, b2, b3, b4, b5, b6, b7;
        unsigned baddr = bbase + ks * 32;
        ldsm4(b0, b1, b2, b3, baddr);
        ldsm4(b4, b5, b6, b7, baddr + 16 * WPADK * 2);
        mma16816(acc[0], a0, a1, a2, a3, b0, b1);
        mma16816(acc[1], a0, a1, a2, a3, b2, b3);
        mma16816(acc[2], a0, a1, a2, a3, b4, b5);
        mma16816(acc[3], a0, a1, a2, a3, b6, b7);
    }
}

// koff: k-tile rotation (0 phase A, 8 phase B) so the barrier-safe input half
// is staged/consumed first. target==0 -> no barrier wait.
template<bool ISA>
__device__ __forceinline__ void do_phase(
    int t, int koff, const __half* __restrict__ in0, const __half* __restrict__ in1,
    __half* __restrict__ hout, float* cr, float* __restrict__ mc,
    unsigned sWu, unsigned wbufu, const float* sBias,
    int lane, int wm, int g, int tg, int B0, int d0, int dgrp,
    unsigned aoffL, unsigned boff,
    int bh, unsigned target)
{
    const int rowbase = B0 + wm * 16;

    // gate bases (phase A: Xp from DRAM — issued early; phase B: bias from SMEM)
    float2 xb[4][2];
    if (ISA) {
        const float* xp = g_Xp + ((size_t)t * 64 + dgrp) * (256 * 32);
#pragma unroll
        for (int nt = 0; nt < 4; nt++)
#pragma unroll
            for (int p = 0; p < 2; p++) {
                int bl = wm * 16 + g + p * 8;
                xb[nt][p] = __ldcg((const float2*)&xp[(size_t)(B0 + bl) * 32 + nt * 8 + 2 * tg]);
            }
    } else {
#pragma unroll
        for (int nt = 0; nt < 4; nt++) {
            float2 bv;
            bv.x = sBias[nt * 8 + 2 * tg];
            bv.y = sBias[nt * 8 + 2 * tg + 1];
            xb[nt][0] = bv; xb[nt][1] = bv;
        }
    }

    float acc[4][4];
#pragma unroll
    for (int nt = 0; nt < 4; nt++)
#pragma unroll
        for (int r = 0; r < 4; r++) acc[nt][r] = 0.f;

    // prologue: stage 3 safe tiles into warp ring
    stage_tile_w(in0, in1, (0 + koff) & 15, wbufu + 0u * (WBUFH * 2), lane, rowbase);
    stage_tile_w(in0, in1, (1 + koff) & 15, wbufu + 1u * (WBUFH * 2), lane, rowbase);
    stage_tile_w(in0, in1, (2 + koff) & 15, wbufu + 2u * (WBUFH * 2), lane, rowbase);

#pragma unroll 4
    for (int i = 0; i < 16; i++) {
        if (i == 5 && target) warp_wait(bh, target);   // before first dependent stage
        if (i < 14)      asm volatile("cp.async.wait_group 2;" ::: "memory");
        else if (i == 14) asm volatile("cp.async.wait_group 1;" ::: "memory");
        else              asm volatile("cp.async.wait_group 0;" ::: "memory");
        if (i < 13)
            stage_tile_w(in0, in1, (i + 3 + koff) & 15,
                         wbufu + (unsigned)(((i + 3) & 3) * (WBUFH * 2)), lane, rowbase);
        consume_tile(acc, wbufu + (unsigned)((i & 3) * (WBUFH * 2)) + aoffL,
                     sWu + boff + (unsigned)(((i + koff) & 15) * 128));
    }

    // register epilogue: thread owns (batch g, g+8) x (d 2tg, 2tg+1), all 4 gates;
    // c-state lives in registers (cr[4]).
#pragma unroll
    for (int p = 0; p < 2; p++) {
        int bl = wm * 16 + g + p * 8;
        float hv[2];
#pragma unroll
        for (int v = 0; v < 2; v++) {
            float gi = acc[0][p * 2 + v] + (v ? xb[0][p].y : xb[0][p].x);
            float gf = acc[1][p * 2 + v] + (v ? xb[1][p].y : xb[1][p].x);
            float gg = acc[2][p * 2 + v] + (v ? xb[2][p].y : xb[2][p].x);
            float go = acc[3][p * 2 + v] + (v ? xb[3][p].y : xb[3][p].x);
            float c = cr[p * 2 + v];
            float cn = sigf(gf) * c + sigf(gi) * tanhf_f(gg);
            cr[p * 2 + v] = cn;
            hv[v] = sigf(go) * tanhf_f(cn);
        }
        __half2 hh = __floats2half2_rn(hv[0], hv[1]);
        *(__half2*)&hout[(size_t)(B0 + bl) * DD + d0 + 2 * tg] = hh;
        if (!ISA) {
            float* mr = mc + ((size_t)(B0 + bl) * FF + t) * MCW + d0 + 2 * tg;
            mr[0] = hv[0]; mr[1] = hv[1];
        }
    }
}

__global__ __launch_bounds__(NTHR, 1) void lstm_persist(float* __restrict__ mc) {
    extern __shared__ __align__(16) unsigned char smraw[];
    __half* sW    = (__half*)smraw;                  // [2][32][WPADK]
    __half* sIn   = sW + 2 * 32 * WPADK;             // [8 warps][4][16][APAD]
    float*  sBias = (float*)(sIn + 8 * WRING);       // [32]

    const int tid  = threadIdx.x;
    const int lane = tid & 31;
    const int wm   = tid >> 5;          // warp = m-tile of 16 batches
    const int g    = lane >> 2;
    const int tg   = lane & 3;
    const int dgrp = blockIdx.x >> 1;   // 0..63
    const int bh   = blockIdx.x & 1;    // batch half
    const int B0   = bh * 128;
    const int d0   = dgrp * 8;

    const unsigned sWu   = (unsigned)__cvta_generic_to_shared(sW);
    const unsigned wbufu = (unsigned)__cvta_generic_to_shared(sIn + wm * WRING);
    // ldmatrix lane offsets (bytes) within a warp stage buffer / weight tile
    const unsigned aoffL = (unsigned)(((lane & 15) * APAD + ((lane >> 4) << 3)) * 2);
    const unsigned boff  = (unsigned)(((((lane >> 1) & 8) | (lane & 7)) * WPADK + (lane & 8)) * 2);

    // one-time: resident fp16 weights (row r = gate*8 + dl), uint4 copies
    for (int i = tid; i < 32 * 128; i += NTHR) {
        int r = i >> 7, c = (i & 127) * 8;
        int grow = (r >> 3) * DD + d0 + (r & 7);
        *(uint4*)&sW[r * WPADK + c] =
            __ldcg((const uint4*)&g_WA16[(size_t)grow * KTOT + c]);
        *(uint4*)&sW[32 * WPADK + r * WPADK + c] =
            __ldcg((const uint4*)&g_WB16[(size_t)grow * KTOT + c]);
    }
    if (tid < 32) sBias[tid] = __ldcg(&g_bias1[(tid >> 3) * DD + d0 + (tid & 7)]);

    // c-state in registers
    float c0r[4], c1r[4];
#pragma unroll
    for (int p = 0; p < 2; p++)
#pragma unroll
        for (int v = 0; v < 2; v++) {
            int bl = wm * 16 + g + p * 8;
            int d = d0 + 2 * tg + v;
            c0r[p * 2 + v] = __ldcg(&g_c0[(size_t)(B0 + bl) * DD + d]);
            c1r[p * 2 + v] = __ldcg(&g_c1[(size_t)(B0 + bl) * DD + d]);
        }
    __syncthreads();

    unsigned ep = 0;
    for (int t = 0; t < FF; t++) {
        int p = t & 1;
        // phase A: layer-0; in = [h0_prev | h1_prev]; safe half = h0 (tiles 0-7)
        do_phase<true>(t, 0, g_h0[p], g_h1[p], g_h0[1 - p], c0r, nullptr,
                       sWu, wbufu, sBias, lane, wm, g, tg, B0, d0, dgrp,
                       aoffL, boff, bh, ep ? ep * 64u : 0u);
        __syncthreads();
        bar_arrive(bh); ep++;
        // phase B: layer-1; in = [h0_new | h1_prev]; safe half = h1 (rotated first)
        do_phase<false>(t, 8, g_h0[1 - p], g_h1[p], g_h1[1 - p], c1r, mc,
                        sWu + 32 * WPADK * 2, wbufu, sBias, lane, wm, g, tg, B0, d0, dgrp,
                        aoffL, boff, bh, ep * 64u);
        __syncthreads();
        bar_arrive(bh); ep++;
    }
}

// ---------------- final decode: preds from stored h1 context ----------------
__global__ __launch_bounds__(256) void dec_kernel(const float* __restrict__ dec_W,
                                                  const float* __restrict__ dec_b,
                                                  float* __restrict__ out_kp, float* __restrict__ mc) {
    __shared__ float sh[4][DD];
    size_t row0 = (size_t)blockIdx.x * 4;
    for (int idx = threadIdx.x; idx < 4 * DD; idx += 256)
        sh[idx >> 9][idx & (DD - 1)] = mc[(row0 + (idx >> 9)) * MCW + (idx & (DD - 1))];
    __syncthreads();
    int r = threadIdx.x >> 6, c = threadIdx.x & 63;
    if (c < NJ3v) {
        float s = dec_b[c];
        for (int k = 0; k < DD; k++) s += sh[r][k] * dec_W[(size_t)k * NJ3v + c];
        size_t row = row0 + r;
        out_kp[row * NJ3v + c] = s;
        mc[row * MCW + DD + c] = s;
    }
}

// ---------------- launch ----------------
extern "C" void kernel_launch(void* const* d_in, const int* in_sizes, int n_in,
                              void* d_out, int out_size) {
    const float* x       = (const float*)d_in[0];
    const float* initp   = (const float*)d_in[1];
    const float* embed_W = (const float*)d_in[2];
    const float* embed_b = (const float*)d_in[3];
    const float* ni_W1   = (const float*)d_in[4];
    const float* ni_b1   = (const float*)d_in[5];
    const float* ni_W2   = (const float*)d_in[6];
    const float* ni_b2   = (const float*)d_in[7];
    const float* ni_W3   = (const float*)d_in[8];
    const float* ni_b3   = (const float*)d_in[9];
    const float* Wih0    = (const float*)d_in[10];
    const float* Whh0    = (const float*)d_in[11];
    const float* bih0    = (const float*)d_in[12];
    const float* bhh0    = (const float*)d_in[13];
    const float* Wih1    = (const float*)d_in[14];
    const float* Whh1    = (const float*)d_in[15];
    const float* bih1    = (const float*)d_in[16];
    const float* bhh1    = (const float*)d_in[17];
    const float* dec_W   = (const float*)d_in[18];
    const float* dec_b   = (const float*)d_in[19];

    float* out = (float*)d_out;
    float* kp = out;                                  // (B,F,17,3)
    float* mc = out + (size_t)BB * FF * NJ3v;         // (B,F,563)

    // one-time precompute (parallel)
    wx_kernel<<<272, 256>>>(embed_W, Wih0);
    bias_kernel<<<8, 256>>>(embed_b, Wih0, bih0, bhh0, bih1, bhh1, dec_b);
    p0c_kernel<<<2048, 256>>>(initp, Wih0);
    packA_kernel<<<8192, 256>>>(Whh0, Wih0, dec_W);
    packB_kernel<<<8192, 256>>>(Wih1, Whh1);
    init1_kernel<<<512, 256>>>(initp, ni_W1, ni_b1);
    init2_kernel<<<1024, 256>>>(ni_W2, ni_b2);
    init3_kernel<<<2048, 256>>>(ni_W3, ni_b3);
    xp_kernel<<<dim3(8, 2048), 256>>>(x);

    // reset split barrier counters (graph-replay deterministic)
    void* barp = nullptr;
    cudaGetSymbolAddress(&barp, g_bar2);
    cudaMemsetAsync(barp, 0, 64 * sizeof(unsigned));

    // persistent tensor-core recurrence
    const int SMEM_TOT = (2 * 32 * WPADK + 8 * WRING) * 2 + 32 * 4;
    static int attr_set = 0;
    if (!attr_set) {
        cudaFuncSetAttribute(lstm_persist, cudaFuncAttributeMaxDynamicSharedMemorySize, SMEM_TOT);
        attr_set = 1;
    }
    lstm_persist<<<NBLK, NTHR, SMEM_TOT>>>(mc);

    // final decode of preds for all (b,t)
    dec_kernel<<<16384, 256>>>(dec_W, dec_b, kp, mc);
}